// round 3
// baseline (speedup 1.0000x reference)
#include <cuda_runtime.h>
#include <cstdint>

// conv_layer_65000035058096
// out[b,v,o] = sum_j sum_k x[b, nb[v*7+j], k] * W[o, j*64+k] + bias[o]
// GEMM view M=B*V (327684), K=448, N=64, gathered A. FFMA2 (f32x2) fp32 path.
//
// Round-3 design: vertex-paired f32x2 (A transposed in smem -> no dup MOVs),
// W pre-duplicated as (w,w) float2 in smem with bank-skewed og groups,
// warp tile 32v x 64o (thread 4v x 16o), per-kk LDS wavefronts 9 vs fma 16.

#define V_TOT 163842
#define NBATCH 2
#define TILE_V 256
#define KCH 16            // k per chunk
#define NCH 28            // 448 / 16
#define SA 260            // As row stride in floats (>=256, mult of 4)
#define SW 80             // Wd row stride in float2
#define GW 20             // og-group stride in float2 (bank skew)

// W transposed to k-major: g_Wt[k*64 + o] = W[o*448 + k]
__device__ float g_Wt[448 * 64];

__global__ void transpose_W_kernel(const float* __restrict__ W) {
    int idx = blockIdx.x * blockDim.x + threadIdx.x;
    if (idx < 448 * 64) {
        int k = idx >> 6, o = idx & 63;
        g_Wt[idx] = W[o * 448 + k];
    }
}

__global__ __launch_bounds__(256, 2)
void sconv_kernel(const float* __restrict__ x,
                  const int* __restrict__ nb,
                  const float* __restrict__ bias,
                  float* __restrict__ out) {
    __shared__ float  As[KCH * SA];       // 16640 B, transposed A: As[k][v]
    __shared__ float2 Wd[KCH * SW];       // 10240 B, dup W: Wd[k][og*GW+oo]=(w,w)
    __shared__ int    nbs[TILE_V * 7];    // 7168 B

    const int t    = threadIdx.x;
    const int lane = t & 31;
    const int warp = t >> 5;
    const int vq   = lane & 7;    // vertex quad within warp's 32 vertices
    const int og   = lane >> 3;   // output group (16 outputs)
    const int batch = blockIdx.y;
    const int v0    = blockIdx.x * TILE_V;
    const long long xbase = (long long)batch * V_TOT;

    // stage neighbor indices once (coalesced)
    {
        const int gbase = v0 * 7;
#pragma unroll
        for (int i = 0; i < 7; ++i) {
            int idx = t + (i << 8);            // 0..1791
            int g = gbase + idx;
            nbs[idx] = (g < V_TOT * 7) ? nb[g] : 0;
        }
    }

    // acc[vpair][oo]: f32x2 over (vertex 2*vpair, 2*vpair+1) for output og*16+oo
    unsigned long long acc[2][16];
#pragma unroll
    for (int vp = 0; vp < 2; ++vp)
#pragma unroll
        for (int oo = 0; oo < 16; ++oo) acc[vp][oo] = 0ull;

    const int fq = t >> 6;   // k-quad 0..3 (constant per warp -> conflict-free STS)
    const int vl = t & 63;   // staging vertex low index

    for (int c = 0; c < NCH; ++c) {
        const int j  = c >> 2;
        const int kb = (c & 3) << 4;
        __syncthreads();   // nbs ready (c==0) / previous compute done (c>0)

        // --- stage W chunk, duplicated: Wd[kk][og*GW + oo] = (w, w)
#pragma unroll
        for (int r = 0; r < 4; ++r) {
            int idx = t + (r << 8);            // 0..1023
            int kk = idx >> 6, o = idx & 63;
            float w = g_Wt[(j * 64 + kb + kk) * 64 + o];
            Wd[kk * SW + (o >> 4) * GW + (o & 15)] = make_float2(w, w);
        }

        // --- stage A transposed: As[kk][v], gather float4 per (v, k-quad)
#pragma unroll
        for (int i = 0; i < 4; ++i) {
            int v  = vl + (i << 6);
            int vg = v0 + v;
            int r  = nbs[(vg < V_TOT ? v : 0) * 7 + j];
            const float4 d = *reinterpret_cast<const float4*>(
                x + ((xbase + r) << 6) + kb + (fq << 2));
            As[((fq << 2) + 0) * SA + v] = d.x;
            As[((fq << 2) + 1) * SA + v] = d.y;
            As[((fq << 2) + 2) * SA + v] = d.z;
            As[((fq << 2) + 3) * SA + v] = d.w;
        }
        __syncthreads();

        // --- compute: per kk: 1 a-LDS.128 + 8 w-LDS.128 + 32 FFMA2
        const float*  arow0 = As + (warp << 5) + (vq << 2);
        const float2* wrow0 = Wd + og * GW;
#pragma unroll 4
        for (int kk = 0; kk < KCH; ++kk) {
            ulonglong2 a = *reinterpret_cast<const ulonglong2*>(arow0 + kk * SA);
            const ulonglong2* wrow =
                reinterpret_cast<const ulonglong2*>(wrow0 + kk * SW);
#pragma unroll
            for (int q = 0; q < 8; ++q) {
                ulonglong2 w = wrow[q];
                asm("fma.rn.f32x2 %0, %1, %2, %0;"
                    : "+l"(acc[0][2 * q])     : "l"(a.x), "l"(w.x));
                asm("fma.rn.f32x2 %0, %1, %2, %0;"
                    : "+l"(acc[0][2 * q + 1]) : "l"(a.x), "l"(w.y));
                asm("fma.rn.f32x2 %0, %1, %2, %0;"
                    : "+l"(acc[1][2 * q])     : "l"(a.y), "l"(w.x));
                asm("fma.rn.f32x2 %0, %1, %2, %0;"
                    : "+l"(acc[1][2 * q + 1]) : "l"(a.y), "l"(w.y));
            }
        }
    }

    // --- epilogue: unpack, add bias, STG.128 (no smem bounce)
    float4 bv[4];
#pragma unroll
    for (int q = 0; q < 4; ++q)
        bv[q] = *reinterpret_cast<const float4*>(bias + og * 16 + (q << 2));

    const int vbase = v0 + (warp << 5) + (vq << 2);
#pragma unroll
    for (int vtx = 0; vtx < 4; ++vtx) {
        if (vbase + vtx < V_TOT) {
            const int vp = vtx >> 1, h = vtx & 1;
            float vals[16];
#pragma unroll
            for (int oo = 0; oo < 16; ++oo) {
                float lo, hi;
                asm("mov.b64 {%0,%1}, %2;" : "=f"(lo), "=f"(hi) : "l"(acc[vp][oo]));
                vals[oo] = h ? hi : lo;
            }
            float* orow = out + ((xbase + vbase + vtx) << 6) + og * 16;
#pragma unroll
            for (int q = 0; q < 4; ++q) {
                float4 o4 = make_float4(vals[4 * q + 0] + bv[q].x,
                                        vals[4 * q + 1] + bv[q].y,
                                        vals[4 * q + 2] + bv[q].z,
                                        vals[4 * q + 3] + bv[q].w);
                *reinterpret_cast<float4*>(orow + (q << 2)) = o4;
            }
        }
    }
}

extern "C" void kernel_launch(void* const* d_in, const int* in_sizes, int n_in,
                              void* d_out, int out_size) {
    const float* x   = (const float*)d_in[0];   // (2, V, 64) f32
    const int*   nb  = (const int*)d_in[1];     // (V*7,) i32 (JAX x64 off)
    const float* W   = (const float*)d_in[2];   // (64, 448) f32
    const float* b   = (const float*)d_in[3];   // (64,) f32
    float*       out = (float*)d_out;           // (2, V, 64) f32

    transpose_W_kernel<<<(448 * 64 + 255) / 256, 256>>>(W);

    dim3 grid((V_TOT + TILE_V - 1) / TILE_V, NBATCH);
    sconv_kernel<<<grid, 256>>>(x, nb, b, out);
}

// round 4
// speedup vs baseline: 1.2694x; 1.2694x over previous
#include <cuda_runtime.h>
#include <cstdint>

// conv_layer_65000035058096
// out[b,v,o] = sum_j sum_k x[b, nb[v*7+j], k] * W[o, j*64+k] + bias[o]
// GEMM M=B*V=327684, K=448, N=64, gathered A. fp32 via fma.rn.f32x2.
//
// R4: vertex-paired f32x2 accs (A transposed in smem), W dup (w,w) bank-skewed,
// per-kk crossbar 5 wf vs 32 fma-cyc per warp -> fma-bound. Register prefetch
// of next chunk hides gather latency. Thread tile 4v x 8o (16 u64 accs).

#define V_TOT 163842
#define NBATCH 2
#define TILE_V 128
#define KCH 16
#define NCH 28           // 448 / KCH
#define SA 132           // As row stride (floats)
#define SWD 80           // Wd row stride (float2): 8 groups * 10
#define GWD 10           // o-group stride (float2), banks {0,20,8,28} per warp

__device__ float g_Wt[448 * 64];   // k-major W: g_Wt[k*64+o] = W[o*448+k]

__global__ void transpose_W_kernel(const float* __restrict__ W) {
    int idx = blockIdx.x * blockDim.x + threadIdx.x;
    if (idx < 448 * 64) {
        int k = idx >> 6, o = idx & 63;
        g_Wt[idx] = W[o * 448 + k];
    }
}

__global__ __launch_bounds__(256, 3)
void sconv_kernel(const float* __restrict__ x,
                  const int* __restrict__ nb,
                  const float* __restrict__ bias,
                  float* __restrict__ out) {
    __shared__ float  As[KCH * SA];      // 8448 B  transposed A: As[k][v]
    __shared__ float2 Wd[KCH * SWD];     // 10240 B dup W: (w,w)
    __shared__ int    nbs[TILE_V * 7];   // 3584 B

    const int t    = threadIdx.x;
    const int lane = t & 31;
    const int warp = t >> 5;
    const int vq   = lane & 7;          // vertex quad (4 consecutive v)
    const int og   = lane >> 3;         // output group (8 outputs)
    const int vwarp = (warp >> 1) << 5; // warp vertex base (0/32/64/96)
    const int obase = (warp & 1) << 5;  // warp output base (0/32)
    const int batch = blockIdx.y;
    const int v0    = blockIdx.x * TILE_V;
    const long long xbase = (long long)batch * V_TOT;

    // ---- stage neighbor indices (coalesced, guarded)
    {
        const int gbase = v0 * 7;
#pragma unroll
        for (int i = 0; i < 4; ++i) {
            int idx = t + (i << 8);
            if (idx < TILE_V * 7) {
                int g = gbase + idx;
                nbs[idx] = (g < V_TOT * 7) ? nb[g] : 0;
            }
        }
    }
    __syncthreads();

    // acc[vp][oo]: f32x2 over vertex pair (2vp, 2vp+1), output obase+og*8+oo
    unsigned long long acc[2][8];
#pragma unroll
    for (int vp = 0; vp < 2; ++vp)
#pragma unroll
        for (int oo = 0; oo < 8; ++oo) acc[vp][oo] = 0ull;

    // prefetch thread mapping
    const int vA = t >> 2;        // 0..63 (two vertices: vA, vA+64)
    const int qA = t & 3;         // k-quad within chunk
    const int kkW = t >> 4;       // 0..15
    const int oW  = (t & 15) << 2;

    float4 pa0, pa1, pw;

    // ---- prefetch chunk 0
    {
        const int j = 0, kb = 0;
        int sv0 = (v0 + vA      < V_TOT) ? vA      : 0;
        int sv1 = (v0 + vA + 64 < V_TOT) ? vA + 64 : 0;
        int r0 = nbs[sv0 * 7 + j], r1 = nbs[sv1 * 7 + j];
        pa0 = *reinterpret_cast<const float4*>(x + ((xbase + r0) << 6) + kb + (qA << 2));
        pa1 = *reinterpret_cast<const float4*>(x + ((xbase + r1) << 6) + kb + (qA << 2));
        pw  = *reinterpret_cast<const float4*>(g_Wt + (j * 64 + kb + kkW) * 64 + oW);
    }

    for (int c = 0; c < NCH; ++c) {
        __syncthreads();   // previous compute done -> smem reusable

        // ---- store prefetched chunk into smem
        {
            float* a0 = As + (qA << 2) * SA + vA;
            a0[0 * SA] = pa0.x; a0[1 * SA] = pa0.y;
            a0[2 * SA] = pa0.z; a0[3 * SA] = pa0.w;
            float* a1 = a0 + 64;
            a1[0 * SA] = pa1.x; a1[1 * SA] = pa1.y;
            a1[2 * SA] = pa1.z; a1[3 * SA] = pa1.w;

            float2* wrow = Wd + kkW * SWD;
            wrow[((oW + 0) >> 3) * GWD + ((oW + 0) & 7)] = make_float2(pw.x, pw.x);
            wrow[((oW + 1) >> 3) * GWD + ((oW + 1) & 7)] = make_float2(pw.y, pw.y);
            wrow[((oW + 2) >> 3) * GWD + ((oW + 2) & 7)] = make_float2(pw.z, pw.z);
            wrow[((oW + 3) >> 3) * GWD + ((oW + 3) & 7)] = make_float2(pw.w, pw.w);
        }
        __syncthreads();

        // ---- prefetch chunk c+1
        if (c + 1 < NCH) {
            const int cn = c + 1;
            const int j  = cn >> 2;
            const int kb = (cn & 3) << 4;
            int sv0 = (v0 + vA      < V_TOT) ? vA      : 0;
            int sv1 = (v0 + vA + 64 < V_TOT) ? vA + 64 : 0;
            int r0 = nbs[sv0 * 7 + j], r1 = nbs[sv1 * 7 + j];
            pa0 = *reinterpret_cast<const float4*>(x + ((xbase + r0) << 6) + kb + (qA << 2));
            pa1 = *reinterpret_cast<const float4*>(x + ((xbase + r1) << 6) + kb + (qA << 2));
            pw  = *reinterpret_cast<const float4*>(g_Wt + (j * 64 + kb + kkW) * 64 + oW);
        }

        // ---- compute: per kk: 1 a-LDS.128 + 4 w-LDS.128 + 16 FFMA2
        const float*  arow = As + vwarp + (vq << 2);
        const float2* wrow = Wd + ((obase >> 3) + og) * GWD;
#pragma unroll
        for (int kk = 0; kk < KCH; ++kk) {
            ulonglong2 a = *reinterpret_cast<const ulonglong2*>(arow + kk * SA);
            const ulonglong2* wr =
                reinterpret_cast<const ulonglong2*>(wrow + kk * SWD);
#pragma unroll
            for (int q = 0; q < 4; ++q) {
                ulonglong2 w = wr[q];
                asm("fma.rn.f32x2 %0, %1, %2, %0;"
                    : "+l"(acc[0][2 * q])     : "l"(a.x), "l"(w.x));
                asm("fma.rn.f32x2 %0, %1, %2, %0;"
                    : "+l"(acc[0][2 * q + 1]) : "l"(a.x), "l"(w.y));
                asm("fma.rn.f32x2 %0, %1, %2, %0;"
                    : "+l"(acc[1][2 * q])     : "l"(a.y), "l"(w.x));
                asm("fma.rn.f32x2 %0, %1, %2, %0;"
                    : "+l"(acc[1][2 * q + 1]) : "l"(a.y), "l"(w.y));
            }
        }
    }

    // ---- epilogue: unpack, +bias, two STG.128 per vertex
    const int ob = obase + (og << 3);
    const float4 bv0 = *reinterpret_cast<const float4*>(bias + ob);
    const float4 bv1 = *reinterpret_cast<const float4*>(bias + ob + 4);

    const int vbase = v0 + vwarp + (vq << 2);
#pragma unroll
    for (int vtx = 0; vtx < 4; ++vtx) {
        if (vbase + vtx < V_TOT) {
            const int vp = vtx >> 1, h = vtx & 1;
            float vals[8];
#pragma unroll
            for (int oo = 0; oo < 8; ++oo) {
                float lo, hi;
                asm("mov.b64 {%0,%1}, %2;" : "=f"(lo), "=f"(hi) : "l"(acc[vp][oo]));
                vals[oo] = h ? hi : lo;
            }
            float* orow = out + ((xbase + vbase + vtx) << 6) + ob;
            *reinterpret_cast<float4*>(orow) =
                make_float4(vals[0] + bv0.x, vals[1] + bv0.y,
                            vals[2] + bv0.z, vals[3] + bv0.w);
            *reinterpret_cast<float4*>(orow + 4) =
                make_float4(vals[4] + bv1.x, vals[5] + bv1.y,
                            vals[6] + bv1.z, vals[7] + bv1.w);
        }
    }
}

extern "C" void kernel_launch(void* const* d_in, const int* in_sizes, int n_in,
                              void* d_out, int out_size) {
    const float* x   = (const float*)d_in[0];   // (2, V, 64) f32
    const int*   nb  = (const int*)d_in[1];     // (V*7,) i32 (JAX x64 off)
    const float* W   = (const float*)d_in[2];   // (64, 448) f32
    const float* b   = (const float*)d_in[3];   // (64,) f32
    float*       out = (float*)d_out;           // (2, V, 64) f32

    transpose_W_kernel<<<(448 * 64 + 255) / 256, 256>>>(W);

    dim3 grid((V_TOT + TILE_V - 1) / TILE_V, NBATCH);
    sconv_kernel<<<grid, 256>>>(x, nb, b, out);
}